// round 2
// baseline (speedup 1.0000x reference)
#include <cuda_runtime.h>
#include <cuda_bf16.h>

// QuantumGate collapses analytically:
//  - RX embedding acts on |+> (eigenstate of X) -> global phase only. Inputs
//    x_t, h_prev, W_in, b_in never affect the output.
//  - RZ is diagonal -> phases only -> irrelevant after |.|^2 on a product state.
//  - The reference's _apply_cnot flips axis=2 after indexing out the control
//    axis; for adjacent c<t gates that axis has size 1, so CNOT(i,i+1) are all
//    NO-OPS. Only CNOT(7,0) (c>t path) actually flips its target.
//    => basis permutation: y_0 = x_0 ^ x_7, y_w = x_w (w>=1).
//  - Bits independent, z_q = -sin(weights[0][q]):
//       ev[0] = z_0 * z_7,  ev[w] = z_w  (w = 1..7)
// So out[b, :] is the SAME 512-vector for every b:
//    r[j] = b_out[j] + sum_w W_out[j][w] * ev[w]
// Kernel = compute r once per block (cheap, redundant) + broadcast-fill 16 MiB.

__global__ void qg_broadcast_kernel(const float* __restrict__ vqc_w,   // [2,8]
                                    const float* __restrict__ W_out,   // [HID,8]
                                    const float* __restrict__ b_out,   // [HID]
                                    float4* __restrict__ out4,
                                    int HID, long long total4) {
    extern __shared__ float r[];   // HID floats
    const int tid = threadIdx.x;

    // Per-qubit Z expectation before CNOTs: z_q = -sin(weights[0][q])
    float z[8];
#pragma unroll
    for (int q = 0; q < 8; ++q) z[q] = -sinf(vqc_w[q]);

    // Reference's effective CNOT permutation: only CNOT(7,0) acts.
    float ev[8];
#pragma unroll
    for (int w = 1; w < 8; ++w) ev[w] = z[w];
    ev[0] = z[0] * z[7];

    // r[j] = b_out[j] + W_out[j,:] . ev
    for (int j = tid; j < HID; j += blockDim.x) {
        const float4* w4 = reinterpret_cast<const float4*>(W_out + (long long)j * 8);
        float4 a = w4[0];
        float4 b = w4[1];
        float acc = b_out[j];
        acc += a.x * ev[0] + a.y * ev[1] + a.z * ev[2] + a.w * ev[3];
        acc += b.x * ev[4] + b.y * ev[5] + b.z * ev[6] + b.w * ev[7];
        r[j] = acc;
    }
    __syncthreads();

    const float4* r4 = reinterpret_cast<const float4*>(r);
    const int n4 = HID >> 2;                         // float4s per row (128)
    const long long stride = (long long)gridDim.x * blockDim.x;
    long long i0 = (long long)blockIdx.x * blockDim.x + tid;

    if ((blockDim.x % n4) == 0) {
        // stride % n4 == 0 -> source column is loop-invariant: pure STG.128 loop
        const float4 val = r4[(int)(i0 % n4)];
        for (long long i = i0; i < total4; i += stride) {
            out4[i] = val;
        }
    } else {
        for (long long i = i0; i < total4; i += stride) {
            out4[i] = r4[(int)(i % n4)];
        }
    }
}

extern "C" void kernel_launch(void* const* d_in, const int* in_sizes, int n_in,
                              void* d_out, int out_size) {
    // metadata order: x_t, h_prev, W_in, b_in, vqc_weights, W_out, b_out
    const float* vqc_w = (const float*)d_in[4];
    const float* W_out = (const float*)d_in[5];
    const float* b_out = (const float*)d_in[6];
    float* out = (float*)d_out;

    const int HID = in_sizes[6];                      // 512
    const long long total4 = (long long)out_size / 4; // 1,048,576 float4 stores

    const int threads = 512;
    long long want_blocks = (total4 + (long long)threads * 4 - 1) / ((long long)threads * 4);
    int blocks = (int)(want_blocks < 1 ? 1 : (want_blocks > 4096 ? 4096 : want_blocks));

    qg_broadcast_kernel<<<blocks, threads, HID * sizeof(float)>>>(
        vqc_w, W_out, b_out, (float4*)out, HID, total4);
}

// round 3
// speedup vs baseline: 1.2657x; 1.2657x over previous
#include <cuda_runtime.h>
#include <cuda_bf16.h>
#include <cstdint>

// Analytic collapse (validated, rel_err 2.3e-7):
//   ev[0] = z0*z7, ev[w>=1] = z_w with z_q = -sin(vqc_weights[0][q])
//   out[b, j] = b_out[j] + W_out[j,:] . ev   -- identical for every row b.
// R2 ncu: store-issue-bound (1M STG.128 x 12cyc issue), DRAM 0.1% (fits L2).
// R3: replicate the 2KB row 16x in shared, emit ONE 32KB cp.async.bulk
// (SMEM -> GMEM) per block. Bulk engine moves the 16.78MB at the LTS cap
// instead of the SIMT store pipe.

#define ROWS_PER_BLK 16

__global__ void qg_tma_bcast_kernel(const float* __restrict__ vqc_w,   // [2,8]
                                    const float* __restrict__ W_out,   // [HID,8]
                                    const float* __restrict__ b_out,   // [HID]
                                    float* __restrict__ out,
                                    int HID, long long rows) {
    extern __shared__ float buf[];   // ROWS_PER_BLK * HID floats
    const int tid = threadIdx.x;

    // z_q = -sin(weights[0][q]); only CNOT(7,0) acts in the reference.
    float z[8];
#pragma unroll
    for (int q = 0; q < 8; ++q) z[q] = -sinf(vqc_w[q]);
    float ev[8];
#pragma unroll
    for (int w = 1; w < 8; ++w) ev[w] = z[w];
    ev[0] = z[0] * z[7];

    // r[j] = b_out[j] + W_out[j,:] . ev ; replicate into all row copies.
    for (int j = tid; j < HID; j += blockDim.x) {
        const float4* w4 = reinterpret_cast<const float4*>(W_out + (long long)j * 8);
        float4 a = w4[0];
        float4 b = w4[1];
        float acc = b_out[j];
        acc += a.x * ev[0] + a.y * ev[1] + a.z * ev[2] + a.w * ev[3];
        acc += b.x * ev[4] + b.y * ev[5] + b.z * ev[6] + b.w * ev[7];
#pragma unroll
        for (int c = 0; c < ROWS_PER_BLK; ++c)
            buf[c * HID + j] = acc;          // consecutive tids -> no conflicts
    }
    __syncthreads();

    long long row0 = (long long)blockIdx.x * ROWS_PER_BLK;
    long long nrows = rows - row0;
    if (nrows <= 0) return;
    if (nrows > ROWS_PER_BLK) nrows = ROWS_PER_BLK;

    if (tid == 0) {
        // Order generic-proxy STS before the async-proxy bulk read.
        asm volatile("fence.proxy.async.shared::cta;" ::: "memory");
        uint32_t saddr;
        asm("{ .reg .u64 t; cvta.to.shared.u64 t, %1; cvt.u32.u64 %0, t; }"
            : "=r"(saddr) : "l"(buf));
        uint64_t gaddr = (uint64_t)(out + row0 * (long long)HID);
        uint32_t bytes = (uint32_t)(nrows * (long long)HID * sizeof(float));
        asm volatile("cp.async.bulk.global.shared::cta.bulk_group [%0], [%1], %2;"
                     :: "l"(gaddr), "r"(saddr), "r"(bytes) : "memory");
        asm volatile("cp.async.bulk.commit_group;" ::: "memory");
        // Must not exit with the bulk store in flight (source smem dies).
        asm volatile("cp.async.bulk.wait_group 0;" ::: "memory");
    }
}

extern "C" void kernel_launch(void* const* d_in, const int* in_sizes, int n_in,
                              void* d_out, int out_size) {
    // metadata order: x_t, h_prev, W_in, b_in, vqc_weights, W_out, b_out
    const float* vqc_w = (const float*)d_in[4];
    const float* W_out = (const float*)d_in[5];
    const float* b_out = (const float*)d_in[6];
    float* out = (float*)d_out;

    const int HID = in_sizes[6];                       // 512
    const long long rows = (long long)out_size / HID;  // 8192

    const int threads = 512;
    const int blocks = (int)((rows + ROWS_PER_BLK - 1) / ROWS_PER_BLK);  // 512
    const size_t smem = (size_t)ROWS_PER_BLK * HID * sizeof(float);      // 32 KB

    qg_tma_bcast_kernel<<<blocks, threads, smem>>>(vqc_w, W_out, b_out, out, HID, rows);
}